// round 1
// baseline (speedup 1.0000x reference)
#include <cuda_runtime.h>
#include <cuda_bf16.h>
#include <math.h>

// ToyMoE: conv stack -> gating -> sparse expert FFN -> combine.
// Inputs (metadata order): x, cw1,cb1, cw2,cb2, cw3,cb3, cw4,cb4, cw5,cb5,
//                          w1,b1, w2,b2, w_gate, w_noise(unused). All fp32.
// Output: y[256*1024] fp32, optionally followed by aux scalar.

#define BATCH 256
#define DFEAT 2048
#define HID   4096
#define OUTD  1024
#define NEXP  16

// ---------------- scratch (static device arrays; no allocation) -------------
__device__ float g_act1[256 * 128 * 32 * 32];
__device__ float g_act2[256 * 256 * 16 * 16];
__device__ float g_act3[256 * 256 * 8 * 8];
__device__ float g_act4[256 * 512 * 4 * 4];
__device__ float g_feats[256 * 2048];
__device__ float g_logits[256 * 16];
__device__ int   g_top_idx[512];
__device__ float g_top_g[512];
__device__ int   g_pair_bs[512];      // b*2+slot, grouped by expert
__device__ int   g_seg_cnt[16];
__device__ int   g_seg_off[16];
__device__ float g_h[512 * 4096];
__device__ float g_probs[512 * 1024];
__device__ float g_aux;

// ---------------- fused conv3x3(SAME)+bias+ReLU+maxpool2 -------------------
// Each thread: one pooled output position (2x2 conv quad) x CPT channels.
template<int CI, int H, int CO, int PT, int CO_BLK, int CPT, int CICH>
__global__ __launch_bounds__(256)
void conv_pool(const float* __restrict__ in, const float* __restrict__ wt,
               const float* __restrict__ bias, float* __restrict__ out)
{
    constexpr int CT = 2 * PT;        // conv tile side
    constexpr int IT = CT + 2;        // input tile side (halo)
    constexpr int HP = H / 2;         // pooled output side
    constexpr int TILES = HP / PT;
    constexpr int POS = PT * PT;
    constexpr int TPP = CO_BLK / CPT;
    static_assert(POS * TPP == 256, "thread count");
    static_assert(CI % CICH == 0, "ci chunk");

    __shared__ float s_in[CICH][IT][IT];
    __shared__ float s_w[CO_BLK][CICH][9];

    const int tid  = threadIdx.x;
    const int tile = blockIdx.x;
    const int ty   = tile / TILES, tx = tile % TILES;
    const int co0  = blockIdx.y * CO_BLK;
    const int n    = blockIdx.z;
    const int pos  = tid % POS;
    const int cog  = tid / POS;
    const int py   = pos / PT, px = pos % PT;

    float acc[CPT][2][2];
#pragma unroll
    for (int c = 0; c < CPT; c++)
#pragma unroll
        for (int i = 0; i < 2; i++)
#pragma unroll
            for (int j = 0; j < 2; j++) acc[c][i][j] = 0.f;

    const int iy0 = ty * CT - 1, ix0 = tx * CT - 1;

    for (int ci0 = 0; ci0 < CI; ci0 += CICH) {
        __syncthreads();
        // load input chunk (zero-padded)
        for (int i = tid; i < CICH * IT * IT; i += 256) {
            int ci = i / (IT * IT);
            int r  = (i / IT) % IT;
            int c  = i % IT;
            int gy = iy0 + r, gx = ix0 + c;
            float v = 0.f;
            if (gy >= 0 && gy < H && gx >= 0 && gx < H)
                v = in[((size_t)(n * CI + ci0 + ci) * H + gy) * H + gx];
            s_in[ci][r][c] = v;
        }
        // load weight chunk
        for (int i = tid; i < CO_BLK * CICH * 9; i += 256) {
            int co = i / (CICH * 9);
            int r  = i % (CICH * 9);
            int ci = r / 9, k = r % 9;
            s_w[co][ci][k] = wt[((size_t)(co0 + co) * CI + ci0 + ci) * 9 + k];
        }
        __syncthreads();

#pragma unroll 2
        for (int ci = 0; ci < CICH; ci++) {
            float r4[4][4];
#pragma unroll
            for (int i = 0; i < 4; i++)
#pragma unroll
                for (int j = 0; j < 4; j++)
                    r4[i][j] = s_in[ci][2 * py + i][2 * px + j];
#pragma unroll
            for (int c = 0; c < CPT; c++) {
                const float* wp = s_w[cog * CPT + c][ci];
                float w0 = wp[0], w1 = wp[1], w2 = wp[2];
                float w3 = wp[3], w4 = wp[4], w5 = wp[5];
                float w6 = wp[6], w7 = wp[7], w8 = wp[8];
#pragma unroll
                for (int i = 0; i < 2; i++)
#pragma unroll
                    for (int j = 0; j < 2; j++) {
                        float a = acc[c][i][j];
                        a = fmaf(r4[i + 0][j + 0], w0, a);
                        a = fmaf(r4[i + 0][j + 1], w1, a);
                        a = fmaf(r4[i + 0][j + 2], w2, a);
                        a = fmaf(r4[i + 1][j + 0], w3, a);
                        a = fmaf(r4[i + 1][j + 1], w4, a);
                        a = fmaf(r4[i + 1][j + 2], w5, a);
                        a = fmaf(r4[i + 2][j + 0], w6, a);
                        a = fmaf(r4[i + 2][j + 1], w7, a);
                        a = fmaf(r4[i + 2][j + 2], w8, a);
                        acc[c][i][j] = a;
                    }
            }
        }
    }

#pragma unroll
    for (int c = 0; c < CPT; c++) {
        int co = co0 + cog * CPT + c;
        float bv = bias[co];
        float m = fmaxf(fmaxf(acc[c][0][0], acc[c][0][1]),
                        fmaxf(acc[c][1][0], acc[c][1][1])) + bv;
        float v = fmaxf(m, 0.f);
        out[((size_t)(n * CO + co) * HP + ty * PT + py) * HP + tx * PT + px] = v;
    }
}

// ---------------- gating ----------------------------------------------------
__global__ __launch_bounds__(128)
void logits_kernel(const float* __restrict__ w_gate)
{
    const int b = blockIdx.x, tid = threadIdx.x;
    __shared__ float s_f[DFEAT];
    __shared__ float s_p[128];
    for (int i = tid; i < DFEAT; i += 128) s_f[i] = g_feats[(size_t)b * DFEAT + i];
    __syncthreads();
    const int e = tid >> 3, j = tid & 7;
    float p = 0.f;
    for (int d = j; d < DFEAT; d += 8)
        p = fmaf(s_f[d], w_gate[d * NEXP + e], p);
    s_p[tid] = p;
    __syncthreads();
    if (j == 0) {
        float s = 0.f;
        for (int q = 0; q < 8; q++) s += s_p[e * 8 + q];
        g_logits[b * NEXP + e] = s;
    }
}

__global__ __launch_bounds__(256)
void gating_kernel()
{
    __shared__ int   s_e[256][2];
    __shared__ float s_g[256][2];
    const int b = threadIdx.x;
    float l[NEXP];
#pragma unroll
    for (int e = 0; e < NEXP; e++) l[e] = g_logits[b * NEXP + e];
    int i1 = 0;
#pragma unroll
    for (int e = 1; e < NEXP; e++) if (l[e] > l[i1]) i1 = e;
    int i2 = (i1 == 0) ? 1 : 0;
#pragma unroll
    for (int e = 0; e < NEXP; e++) if (e != i1 && l[e] > l[i2]) i2 = e;
    float z = expf(l[i2] - l[i1]);
    float den = 1.f + z;
    float g1 = 1.f / den, g2 = z / den;
    s_e[b][0] = i1; s_e[b][1] = i2;
    s_g[b][0] = g1; s_g[b][1] = g2;
    g_top_idx[b * 2 + 0] = i1; g_top_idx[b * 2 + 1] = i2;
    g_top_g[b * 2 + 0] = g1;   g_top_g[b * 2 + 1] = g2;
    __syncthreads();
    if (b == 0) {
        float imp[NEXP], lod[NEXP];
        int cnt[NEXP];
        for (int e = 0; e < NEXP; e++) { imp[e] = 0.f; lod[e] = 0.f; cnt[e] = 0; }
        for (int t = 0; t < 256; t++)
            for (int s = 0; s < 2; s++) {
                float g = s_g[t][s]; int e = s_e[t][s];
                imp[e] += g;
                if (g > 0.f) { lod[e] += 1.f; cnt[e]++; }
            }
        // cv^2 of importance and load
        float mi = 0.f, ml = 0.f;
        for (int e = 0; e < NEXP; e++) { mi += imp[e]; ml += lod[e]; }
        mi /= NEXP; ml /= NEXP;
        float vi = 0.f, vl = 0.f;
        for (int e = 0; e < NEXP; e++) {
            float a = imp[e] - mi, c = lod[e] - ml;
            vi += a * a; vl += c * c;
        }
        vi /= NEXP; vl /= NEXP;
        g_aux = 0.01f * (vi / (mi * mi + 1e-10f) + vl / (ml * ml + 1e-10f));
        // expert-grouped pair list (deterministic)
        int off[NEXP], fill[NEXP], run = 0;
        for (int e = 0; e < NEXP; e++) {
            off[e] = run; fill[e] = 0; run += cnt[e];
            g_seg_off[e] = off[e]; g_seg_cnt[e] = cnt[e];
        }
        for (int t = 0; t < 256; t++)
            for (int s = 0; s < 2; s++) {
                float g = s_g[t][s];
                if (g > 0.f) {
                    int e = s_e[t][s];
                    g_pair_bs[off[e] + fill[e]++] = t * 2 + s;
                }
            }
    }
}

// ---------------- expert FFN fc1 (grouped by expert) -----------------------
__global__ __launch_bounds__(128)
void ffn1_kernel(const float* __restrict__ w1, const float* __restrict__ b1)
{
    const int e = blockIdx.y;
    const int cnt = g_seg_cnt[e];
    if (cnt == 0) return;
    const int off = g_seg_off[e];
    const int tid = threadIdx.x;
    const int colA = blockIdx.x * 256 + tid;
    const int colB = colA + 128;
    __shared__ float s_f[16][32];
    __shared__ int s_bs[16];

    for (int t0 = 0; t0 < cnt; t0 += 16) {
        if (tid < 16) s_bs[tid] = (t0 + tid < cnt) ? g_pair_bs[off + t0 + tid] : -1;
        __syncthreads();
        float accA[16], accB[16];
#pragma unroll
        for (int t = 0; t < 16; t++) { accA[t] = 0.f; accB[t] = 0.f; }

        for (int d0 = 0; d0 < DFEAT; d0 += 32) {
#pragma unroll
            for (int q = 0; q < 4; q++) {
                int i = tid + q * 128;
                int t = i >> 5, dd = i & 31;
                int bs = s_bs[t];
                s_f[t][dd] = (bs >= 0) ? g_feats[(size_t)(bs >> 1) * DFEAT + d0 + dd] : 0.f;
            }
            __syncthreads();
#pragma unroll 8
            for (int dd = 0; dd < 32; dd++) {
                size_t ridx = ((size_t)e * DFEAT + d0 + dd) * HID;
                float wa = w1[ridx + colA];
                float wb = w1[ridx + colB];
#pragma unroll
                for (int t = 0; t < 16; t++) {
                    float f = s_f[t][dd];
                    accA[t] = fmaf(f, wa, accA[t]);
                    accB[t] = fmaf(f, wb, accB[t]);
                }
            }
            __syncthreads();
        }
        float bva = b1[e * HID + colA], bvb = b1[e * HID + colB];
#pragma unroll
        for (int t = 0; t < 16; t++) {
            int bs = s_bs[t];
            if (bs >= 0) {
                g_h[(size_t)bs * HID + colA] = fmaxf(accA[t] + bva, 0.f);
                g_h[(size_t)bs * HID + colB] = fmaxf(accB[t] + bvb, 0.f);
            }
        }
        __syncthreads();
    }
}

// ---------------- expert FFN fc2 + softmax ----------------------------------
__global__ __launch_bounds__(256)
void ffn2_kernel(const float* __restrict__ w2, const float* __restrict__ b2)
{
    const int p = blockIdx.x;
    const float g = g_top_g[p];
    if (g <= 0.f) return;
    const int e = g_top_idx[p];
    const int tid = threadIdx.x;
    __shared__ float s_h[HID];
    __shared__ float s_red[256];
    for (int i = tid; i < HID; i += 256) s_h[i] = g_h[(size_t)p * HID + i];
    __syncthreads();

    float acc0 = 0.f, acc1 = 0.f, acc2 = 0.f, acc3 = 0.f;
    const float* wp = w2 + (size_t)e * HID * OUTD + tid;
#pragma unroll 4
    for (int d = 0; d < HID; d++) {
        float hv = s_h[d];
        const float* wr = wp + (size_t)d * OUTD;
        acc0 = fmaf(hv, wr[0],   acc0);
        acc1 = fmaf(hv, wr[256], acc1);
        acc2 = fmaf(hv, wr[512], acc2);
        acc3 = fmaf(hv, wr[768], acc3);
    }
    float o[4];
    o[0] = acc0 + b2[e * OUTD + tid];
    o[1] = acc1 + b2[e * OUTD + tid + 256];
    o[2] = acc2 + b2[e * OUTD + tid + 512];
    o[3] = acc3 + b2[e * OUTD + tid + 768];
    float vmax = fmaxf(fmaxf(o[0], o[1]), fmaxf(o[2], o[3]));
    s_red[tid] = vmax;
    __syncthreads();
    for (int s = 128; s > 0; s >>= 1) {
        if (tid < s) s_red[tid] = fmaxf(s_red[tid], s_red[tid + s]);
        __syncthreads();
    }
    float m = s_red[0];
    __syncthreads();
    float ssum = 0.f;
#pragma unroll
    for (int c = 0; c < 4; c++) { o[c] = expf(o[c] - m); ssum += o[c]; }
    s_red[tid] = ssum;
    __syncthreads();
    for (int s = 128; s > 0; s >>= 1) {
        if (tid < s) s_red[tid] += s_red[tid + s];
        __syncthreads();
    }
    float inv = 1.f / s_red[0];
#pragma unroll
    for (int c = 0; c < 4; c++)
        g_probs[(size_t)p * OUTD + tid + c * 256] = o[c] * inv;
}

// ---------------- combine + aux ---------------------------------------------
__global__ __launch_bounds__(256)
void combine_kernel(float* __restrict__ out, int out_size)
{
    const int b = blockIdx.x, tid = threadIdx.x;
#pragma unroll
    for (int c = 0; c < 4; c++) {
        int col = tid + c * 256;
        float v = 0.f;
#pragma unroll
        for (int s = 0; s < 2; s++) {
            float g = g_top_g[b * 2 + s];
            if (g > 0.f)
                v = fmaf(g, g_probs[(size_t)(b * 2 + s) * OUTD + col], v);
        }
        out[(size_t)b * OUTD + col] = v;
    }
    if (b == 0 && tid == 0) {
        for (int i = BATCH * OUTD; i < out_size; i++) out[i] = g_aux;
    }
}

// ---------------- launch -----------------------------------------------------
extern "C" void kernel_launch(void* const* d_in, const int* in_sizes, int n_in,
                              void* d_out, int out_size)
{
    const float* x   = (const float*)d_in[0];
    const float* cw1 = (const float*)d_in[1];
    const float* cb1 = (const float*)d_in[2];
    const float* cw2 = (const float*)d_in[3];
    const float* cb2 = (const float*)d_in[4];
    const float* cw3 = (const float*)d_in[5];
    const float* cb3 = (const float*)d_in[6];
    const float* cw4 = (const float*)d_in[7];
    const float* cb4 = (const float*)d_in[8];
    const float* cw5 = (const float*)d_in[9];
    const float* cb5 = (const float*)d_in[10];
    const float* w1  = (const float*)d_in[11];
    const float* b1  = (const float*)d_in[12];
    const float* w2  = (const float*)d_in[13];
    const float* b2  = (const float*)d_in[14];
    const float* w_gate = (const float*)d_in[15];
    (void)n_in; (void)in_sizes;

    float *act1, *act2, *act3, *act4, *feats;
    cudaGetSymbolAddress((void**)&act1, g_act1);
    cudaGetSymbolAddress((void**)&act2, g_act2);
    cudaGetSymbolAddress((void**)&act3, g_act3);
    cudaGetSymbolAddress((void**)&act4, g_act4);
    cudaGetSymbolAddress((void**)&feats, g_feats);

    // conv stack (fused conv+relu+pool)
    conv_pool<3,   64, 128, 8,  32, 8, 3 ><<<dim3(16, 4, BATCH), 256>>>(x,    cw1, cb1, act1);
    conv_pool<128, 32, 256, 8,  32, 8, 16><<<dim3(4,  8, BATCH), 256>>>(act1, cw2, cb2, act2);
    conv_pool<256, 16, 256, 8,  32, 8, 16><<<dim3(1,  8, BATCH), 256>>>(act2, cw3, cb3, act3);
    conv_pool<256, 8,  512, 4,  64, 4, 8 ><<<dim3(1,  8, BATCH), 256>>>(act3, cw4, cb4, act4);
    conv_pool<512, 4,  512, 2, 128, 2, 4 ><<<dim3(1,  4, BATCH), 256>>>(act4, cw5, cb5, feats);

    // gating
    logits_kernel<<<BATCH, 128>>>(w_gate);
    gating_kernel<<<1, 256>>>();

    // sparse expert FFN
    ffn1_kernel<<<dim3(HID / 256, NEXP), 128>>>(w1, b1);
    ffn2_kernel<<<512, 256>>>(w2, b2);

    // combine + aux
    combine_kernel<<<BATCH, 256>>>((float*)d_out, out_size);
}